// round 8
// baseline (speedup 1.0000x reference)
#include <cuda_runtime.h>
#include <cstdint>

#define NBLK 128
#define NTHR 256
#define HDIM 512
#define BDIM 128
#define TIN  512
#define TOT  544
#define KH   (HDIM*BDIM)          // 65536 floats per state buffer

#define SMEM_FLOATS 28608
#define SMEM_BYTES  (SMEM_FLOATS*4)

__device__ float    g_h1t[2*KH];   // [buf][k][b]   transposed
__device__ float    g_h2t[2*KH];   // [buf][k][b]
__device__ float    g_h2n[2*KH];   // [buf][b][k]   row-major copy (for output dots)
__device__ unsigned g_bar;

static __device__ __forceinline__ unsigned long long dup2(float x){
    unsigned long long r; unsigned v = __float_as_uint(x);
    asm("mov.b64 %0, {%1, %1};" : "=l"(r) : "r"(v));
    return r;
}
static __device__ __forceinline__ void fma2(unsigned long long& d,
                                            unsigned long long a, unsigned long long b){
    asm("fma.rn.f32x2 %0, %1, %2, %0;" : "+l"(d) : "l"(a), "l"(b));
}
static __device__ __forceinline__ void addf2(unsigned long long& d, unsigned long long s){
    asm("add.rn.f32x2 %0, %0, %1;" : "+l"(d) : "l"(s));
}
static __device__ __forceinline__ float lo32(unsigned long long v){
    unsigned lo, hi; asm("mov.b64 {%0, %1}, %2;" : "=r"(lo), "=r"(hi) : "l"(v));
    return __uint_as_float(lo);
}
static __device__ __forceinline__ float hi32(unsigned long long v){
    unsigned lo, hi; asm("mov.b64 {%0, %1}, %2;" : "=r"(lo), "=r"(hi) : "l"(v));
    return __uint_as_float(hi);
}
static __device__ __forceinline__ float sigf(float x){ return 1.0f/(1.0f+__expf(-x)); }
static __device__ __forceinline__ float tfast(float x){ return 2.0f*sigf(2.0f*x) - 1.0f; }

static __device__ __forceinline__ void grid_barrier(unsigned& gen){
    __threadfence();
    __syncthreads();
    if (threadIdx.x == 0){
        unsigned target = gen + NBLK;
        atomicAdd(&g_bar, 1u);
        unsigned v;
        do { asm volatile("ld.acquire.gpu.u32 %0, [%1];" : "=r"(v) : "l"(&g_bar)); }
        while (v < target);
    }
    gen += NBLK;
    __syncthreads();
}

// acc[0][b] packs (i,f) partial sums, acc[1][b] packs (g,o), for 4 batches b0..b0+3,
// over k in [k0, k0+256). Weights in smem [k][16] (gate order i,f,g,o per unit),
// h in gmem transposed [k][128] (read via L2 — cross-CTA coherent).
static __device__ __forceinline__ void gemm_acc_t(
    const float* __restrict__ wsm, const float* __restrict__ ht,
    unsigned long long (&acc)[2][4], int u, int b0, int k0)
{
    #pragma unroll 4
    for (int k = k0; k < k0 + HDIM/2; ++k){
        ulonglong2 w = *reinterpret_cast<const ulonglong2*>(wsm + (k<<4) + (u<<2));
        float4 hv = __ldcg(reinterpret_cast<const float4*>(ht + ((size_t)k<<7) + b0));
        unsigned long long h0 = dup2(hv.x), h1 = dup2(hv.y);
        unsigned long long h2 = dup2(hv.z), h3 = dup2(hv.w);
        fma2(acc[0][0], w.x, h0); fma2(acc[1][0], w.y, h0);
        fma2(acc[0][1], w.x, h1); fma2(acc[1][1], w.y, h1);
        fma2(acc[0][2], w.x, h2); fma2(acc[1][2], w.y, h2);
        fma2(acc[0][3], w.x, h3); fma2(acc[1][3], w.y, h3);
    }
}

// Combine the two K-halves: upper half (tid>=128) posts, lower half adds.
static __device__ __forceinline__ void ksplit_reduce(
    unsigned long long* s_red2, unsigned long long (&acc)[2][4], int tid)
{
    if (tid >= 128){
        unsigned long long* p = s_red2 + (size_t)(tid - 128)*8;
        p[0]=acc[0][0]; p[1]=acc[1][0]; p[2]=acc[0][1]; p[3]=acc[1][1];
        p[4]=acc[0][2]; p[5]=acc[1][2]; p[6]=acc[0][3]; p[7]=acc[1][3];
    }
    __syncthreads();
    if (tid < 128){
        unsigned long long* p = s_red2 + (size_t)tid*8;
        addf2(acc[0][0],p[0]); addf2(acc[1][0],p[1]);
        addf2(acc[0][1],p[2]); addf2(acc[1][1],p[3]);
        addf2(acc[0][2],p[4]); addf2(acc[1][2],p[5]);
        addf2(acc[0][3],p[6]); addf2(acc[1][3],p[7]);
    }
}

// out[b] = dot(h2n[b,:], Wout) + bias, warp 0 only. h2n is row-major [b][k].
static __device__ __forceinline__ void out_one(
    const float* __restrict__ h2n, const float* __restrict__ s_wout,
    float bout, int b, float* dst)
{
    const int lane = threadIdx.x;
    const float4* hp = reinterpret_cast<const float4*>(h2n) + (size_t)b*(HDIM/4);
    const float4* wp = reinterpret_cast<const float4*>(s_wout);
    float s = 0.f;
    #pragma unroll
    for (int q = lane; q < HDIM/4; q += 32){
        float4 hv = __ldcg(hp + q); float4 w = wp[q];
        s += hv.x*w.x + hv.y*w.y + hv.z*w.z + hv.w*w.w;
    }
    #pragma unroll
    for (int o = 16; o; o >>= 1) s += __shfl_xor_sync(0xffffffffu, s, o);
    if (lane == 0) *dst = s + bout;
}

__global__ void lstm_reset(){ g_bar = 0u; }

__global__ void __launch_bounds__(NTHR, 1) lstm_persist(
    const float* __restrict__ xg,
    const float* __restrict__ Wih1, const float* __restrict__ Whh1,
    const float* __restrict__ bih1, const float* __restrict__ bhh1,
    const float* __restrict__ Wih2, const float* __restrict__ Whh2,
    const float* __restrict__ bih2, const float* __restrict__ bhh2,
    const float* __restrict__ Wout, const float* __restrict__ boutp,
    float* __restrict__ outg)
{
    extern __shared__ float sm[];
    float* s_ws1  = sm;                 // [512][16] transposed, gate-pair order
    float* s_ws2i = sm + 8192;
    float* s_ws2h = sm + 16384;
    float* s_wout = sm + 24576;         // 512
    float* s_wih1 = sm + 25088;         // 16
    float* s_b1   = sm + 25104;         // 16
    float* s_b2   = sm + 25120;         // 16
    float* s_c1   = sm + 25136;         // [4u][128b]
    float* s_c2   = sm + 25648;         // 512
    float* s_xs   = sm + 26160;         // 128
    float* s_red  = sm + 26288;         // 256
    float* s_bout = sm + 26544;         // 1 (+pad)
    unsigned long long* s_red2 =
        reinterpret_cast<unsigned long long*>(sm + 26560);  // 128*8 u64

    const int tid = threadIdx.x;
    const int blk = blockIdx.x;
    const int U0  = blk * 4;
    const int u   = tid & 3;
    const int bg  = (tid >> 2) & 31;
    const int kc  = tid >> 7;
    const int b0  = bg * 4;
    const int k0  = kc * (HDIM/2);

    // ---- one-time staging ----
    {
        for (int idx = tid; idx < 16*128; idx += NTHR){
            int r = idx >> 7, k4 = idx & 127;          // r = u*4+g
            int uu = r >> 2, gg = r & 3;
            int j = gg*HDIM + U0 + uu;                  // global gate row
            float4 a = reinterpret_cast<const float4*>(Whh1 + (size_t)j*HDIM)[k4];
            float4 b = reinterpret_cast<const float4*>(Wih2 + (size_t)j*HDIM)[k4];
            float4 c = reinterpret_cast<const float4*>(Whh2 + (size_t)j*HDIM)[k4];
            int base = (4*k4)*16 + r;
            s_ws1 [base     ] = a.x; s_ws1 [base+16] = a.y;
            s_ws1 [base+32  ] = a.z; s_ws1 [base+48] = a.w;
            s_ws2i[base     ] = b.x; s_ws2i[base+16] = b.y;
            s_ws2i[base+32  ] = b.z; s_ws2i[base+48] = b.w;
            s_ws2h[base     ] = c.x; s_ws2h[base+16] = c.y;
            s_ws2h[base+32  ] = c.z; s_ws2h[base+48] = c.w;
        }
        if (tid < 16){
            int uu = tid >> 2, gg = tid & 3;
            int j = gg*HDIM + U0 + uu;
            s_wih1[tid] = Wih1[j];
            s_b1[tid]   = bih1[j] + bhh1[j];
            s_b2[tid]   = bih2[j] + bhh2[j];
        }
        if (tid < 128)
            reinterpret_cast<float4*>(s_wout)[tid] =
                reinterpret_cast<const float4*>(Wout)[tid];
        if (tid == 0) s_bout[0] = boutp[0];
        s_c1[tid] = 0.f; s_c1[tid+256] = 0.f;
        s_c2[tid] = 0.f; s_c2[tid+256] = 0.f;
        for (int i = tid; i < 4*BDIM; i += NTHR){
            int kk = U0 + (i >> 7), bb = i & 127;
            size_t o  = (size_t)kk*BDIM + bb;
            size_t on = (size_t)bb*HDIM + kk;
            g_h1t[o] = 0.f; g_h1t[KH+o] = 0.f;
            g_h2t[o] = 0.f; g_h2t[KH+o] = 0.f;
            g_h2n[on]= 0.f; g_h2n[KH+on]= 0.f;
        }
    }
    unsigned gen = 0;
    grid_barrier(gen);

    for (int t = 0; t < TOT; ++t){
        const int cur = t & 1, prv = cur ^ 1;
        const float* h1r  = g_h1t + (size_t)prv*KH;
        float*       h1w  = g_h1t + (size_t)cur*KH;
        const float* h2r  = g_h2t + (size_t)prv*KH;
        float*       h2w  = g_h2t + (size_t)cur*KH;
        const float* h2nr = g_h2n + (size_t)prv*KH;
        float*       h2nw = g_h2n + (size_t)cur*KH;

        // Phase X: x_t into s_xs; emit out(t-1)
        if (t < TIN){
            if (tid < BDIM) s_xs[tid] = xg[(size_t)tid*TIN + t];
            if (t > 0 && tid < 32)
                out_one(h2nr, s_wout, s_bout[0], blk, outg + (size_t)blk*TOT + (t-1));
        } else {
            int b = tid & 127, half = tid >> 7;
            const float* hp = h2r + (size_t)half*(HDIM/2)*BDIM + b;
            const float* wp = s_wout + half*(HDIM/2);
            float s = 0.f;
            #pragma unroll 8
            for (int q = 0; q < HDIM/2; ++q)
                s += __ldcg(hp + (size_t)q*BDIM) * wp[q];
            s_red[tid] = s;
            __syncthreads();
            if (tid < BDIM) s_xs[tid] = s_red[tid] + s_red[tid+128] + s_bout[0];
        }
        __syncthreads();
        if (t >= TIN && tid == 0) outg[(size_t)blk*TOT + (t-1)] = s_xs[blk];

        // Phase 1: layer-1 gates + update
        {
            unsigned long long acc[2][4] = {};
            gemm_acc_t(s_ws1, h1r, acc, u, b0, k0);
            ksplit_reduce(s_red2, acc, tid);
            if (tid < 128){
                float4 hv; float* hvp = &hv.x;
                float4 cold = *reinterpret_cast<float4*>(&s_c1[u*BDIM + b0]);
                float* cop = &cold.x;
                #pragma unroll
                for (int bi = 0; bi < 4; ++bi){
                    float xv = s_xs[b0 + bi];
                    float vi = lo32(acc[0][bi]) + s_b1[u*4+0] + xv*s_wih1[u*4+0];
                    float vf = hi32(acc[0][bi]) + s_b1[u*4+1] + xv*s_wih1[u*4+1];
                    float vg = lo32(acc[1][bi]) + s_b1[u*4+2] + xv*s_wih1[u*4+2];
                    float vo = hi32(acc[1][bi]) + s_b1[u*4+3] + xv*s_wih1[u*4+3];
                    float c  = sigf(vf)*cop[bi] + sigf(vi)*tfast(vg);
                    cop[bi]  = c;
                    hvp[bi]  = sigf(vo)*tfast(c);
                }
                *reinterpret_cast<float4*>(&s_c1[u*BDIM + b0]) = cold;
                *reinterpret_cast<float4*>(&h1w[(size_t)(U0+u)*BDIM + b0]) = hv;
            }
        }
        grid_barrier(gen);

        // Phase 2: layer-2 gates (K = h1_new, then h2_prev) + update
        {
            unsigned long long acc[2][4] = {};
            gemm_acc_t(s_ws2i, h1w, acc, u, b0, k0);
            gemm_acc_t(s_ws2h, h2r, acc, u, b0, k0);
            ksplit_reduce(s_red2, acc, tid);
            if (tid < 128){
                float4 hv; float* hvp = &hv.x;
                float4 cold = *reinterpret_cast<float4*>(&s_c2[u*BDIM + b0]);
                float* cop = &cold.x;
                #pragma unroll
                for (int bi = 0; bi < 4; ++bi){
                    float vi = lo32(acc[0][bi]) + s_b2[u*4+0];
                    float vf = hi32(acc[0][bi]) + s_b2[u*4+1];
                    float vg = lo32(acc[1][bi]) + s_b2[u*4+2];
                    float vo = hi32(acc[1][bi]) + s_b2[u*4+3];
                    float c  = sigf(vf)*cop[bi] + sigf(vi)*tfast(vg);
                    cop[bi]  = c;
                    hvp[bi]  = sigf(vo)*tfast(c);
                }
                *reinterpret_cast<float4*>(&s_c2[u*BDIM + b0]) = cold;
                *reinterpret_cast<float4*>(&h2w[(size_t)(U0+u)*BDIM + b0]) = hv;
                h2nw[(size_t)(b0+0)*HDIM + U0 + u] = hv.x;
                h2nw[(size_t)(b0+1)*HDIM + U0 + u] = hv.y;
                h2nw[(size_t)(b0+2)*HDIM + U0 + u] = hv.z;
                h2nw[(size_t)(b0+3)*HDIM + U0 + u] = hv.w;
            }
        }
        grid_barrier(gen);
    }

    if (tid < 32)
        out_one(g_h2n + (size_t)((TOT-1)&1)*KH, s_wout, s_bout[0],
                blk, outg + (size_t)blk*TOT + (TOT-1));
}

extern "C" void kernel_launch(void* const* d_in, const int* in_sizes, int n_in,
                              void* d_out, int out_size){
    (void)in_sizes; (void)n_in; (void)out_size;
    static int smem_ok = 0;
    if (!smem_ok){
        cudaFuncSetAttribute(lstm_persist,
                             cudaFuncAttributeMaxDynamicSharedMemorySize, SMEM_BYTES);
        smem_ok = 1;
    }
    const float* x    = (const float*)d_in[0];
    const float* Wih1 = (const float*)d_in[1];
    const float* Whh1 = (const float*)d_in[2];
    const float* bih1 = (const float*)d_in[3];
    const float* bhh1 = (const float*)d_in[4];
    const float* Wih2 = (const float*)d_in[5];
    const float* Whh2 = (const float*)d_in[6];
    const float* bih2 = (const float*)d_in[7];
    const float* bhh2 = (const float*)d_in[8];
    const float* Wout = (const float*)d_in[9];
    const float* bout = (const float*)d_in[10];
    float* out = (float*)d_out;

    lstm_reset<<<1, 1>>>();
    lstm_persist<<<NBLK, NTHR, SMEM_BYTES>>>(
        x, Wih1, Whh1, bih1, bhh1, Wih2, Whh2, bih2, bhh2, Wout, bout, out);
}

// round 9
// speedup vs baseline: 1.2375x; 1.2375x over previous
#include <cuda_runtime.h>
#include <cstdint>

#define NBLK 128
#define NTHR 512
#define HDIM 512
#define BDIM 128
#define TIN  512
#define TOT  544
#define KH   (HDIM*BDIM)

// SMEM float offsets
#define OFF_W1    0        // [512][32]: k*32 + u*8 + g*2 + {0,1}, dup'd
#define OFF_W2I   16384
#define OFF_W2H   32768
#define OFF_WOUT  49152    // 512
#define OFF_WIH1  49664    // 16
#define OFF_B1    49680    // 16
#define OFF_B2    49696    // 16
#define OFF_C1    49712    // 512
#define OFF_C2    50224    // 512
#define OFF_XS    50736    // 128
#define OFF_RED   50864    // 512
#define OFF_BOUT  51376    // 2 (pad)
#define OFF_RED2  51378    // 3*128*8 u64 = 6144 floats
#define SMEM_FLOATS (51378 + 6144)
#define SMEM_BYTES  (SMEM_FLOATS*4)

__device__ float    g_h1t[2*KH];   // [buf][k][b]
__device__ float    g_h2t[2*KH];   // [buf][k][b]
__device__ float    g_h2n[2*KH];   // [buf][b][k]
__device__ unsigned g_bar;

static __device__ __forceinline__ void fma2(unsigned long long& d,
                                            unsigned long long a, unsigned long long b){
    asm("fma.rn.f32x2 %0, %1, %2, %0;" : "+l"(d) : "l"(a), "l"(b));
}
static __device__ __forceinline__ void addf2(unsigned long long& d, unsigned long long s){
    asm("add.rn.f32x2 %0, %0, %1;" : "+l"(d) : "l"(s));
}
static __device__ __forceinline__ float lo32(unsigned long long v){
    unsigned lo, hi; asm("mov.b64 {%0, %1}, %2;" : "=r"(lo), "=r"(hi) : "l"(v));
    return __uint_as_float(lo);
}
static __device__ __forceinline__ float hi32(unsigned long long v){
    unsigned lo, hi; asm("mov.b64 {%0, %1}, %2;" : "=r"(lo), "=r"(hi) : "l"(v));
    return __uint_as_float(hi);
}
static __device__ __forceinline__ float sigf(float x){ return 1.0f/(1.0f+__expf(-x)); }
static __device__ __forceinline__ float tfast(float x){ return 2.0f*sigf(2.0f*x) - 1.0f; }

static __device__ __forceinline__ void grid_barrier(unsigned& gen){
    __threadfence();
    __syncthreads();
    if (threadIdx.x == 0){
        unsigned target = gen + NBLK;
        atomicAdd(&g_bar, 1u);
        unsigned v;
        do { asm volatile("ld.acquire.gpu.u32 %0, [%1];" : "=r"(v) : "l"(&g_bar)); }
        while (v < target);
    }
    gen += NBLK;
    __syncthreads();
}

// 4 gates (unit u) x 4 batches (2 packed pairs), k in [k0, k0+128).
// w dup'd in smem: LDS.128 -> (w,w) pairs. h transposed [k][128]: LDG.128 -> 2 batch pairs.
// 11 instr / 16 MAC, no ALU movs.
static __device__ __forceinline__ void gemm2(
    const float* __restrict__ wsm, const float* __restrict__ ht,
    unsigned long long (&acc)[4][2], int u, int b0, int k0)
{
    const ulonglong2* wp = reinterpret_cast<const ulonglong2*>(wsm) + u*2;
    const longlong2*  hp = reinterpret_cast<const longlong2*>(ht + b0);
    #pragma unroll 8
    for (int k = k0; k < k0 + HDIM/4; ++k){
        ulonglong2 w01 = wp[k*8];        // (wi,wi),(wf,wf)
        ulonglong2 w23 = wp[k*8 + 1];    // (wg,wg),(wo,wo)
        longlong2  hv  = __ldcg(hp + k*32);
        unsigned long long hx = (unsigned long long)hv.x;
        unsigned long long hy = (unsigned long long)hv.y;
        fma2(acc[0][0], w01.x, hx); fma2(acc[0][1], w01.x, hy);
        fma2(acc[1][0], w01.y, hx); fma2(acc[1][1], w01.y, hy);
        fma2(acc[2][0], w23.x, hx); fma2(acc[2][1], w23.x, hy);
        fma2(acc[3][0], w23.y, hx); fma2(acc[3][1], w23.y, hy);
    }
}

// kc=1..3 post partials, kc=0 accumulates.
static __device__ __forceinline__ void ksplit_reduce(
    unsigned long long* s_red2, unsigned long long (&acc)[4][2], int tid, int kc)
{
    if (kc){
        unsigned long long* p = s_red2 + ((size_t)(kc-1)*128 + (tid & 127))*8;
        p[0]=acc[0][0]; p[1]=acc[0][1]; p[2]=acc[1][0]; p[3]=acc[1][1];
        p[4]=acc[2][0]; p[5]=acc[2][1]; p[6]=acc[3][0]; p[7]=acc[3][1];
    }
    __syncthreads();
    if (kc == 0){
        #pragma unroll
        for (int s = 0; s < 3; ++s){
            unsigned long long* p = s_red2 + ((size_t)s*128 + tid)*8;
            addf2(acc[0][0],p[0]); addf2(acc[0][1],p[1]);
            addf2(acc[1][0],p[2]); addf2(acc[1][1],p[3]);
            addf2(acc[2][0],p[4]); addf2(acc[2][1],p[5]);
            addf2(acc[3][0],p[6]); addf2(acc[3][1],p[7]);
        }
    }
}

static __device__ __forceinline__ void out_one(
    const float* __restrict__ h2n, const float* __restrict__ s_wout,
    float bout, int b, float* dst)
{
    const int lane = threadIdx.x;  // caller: tid < 32
    const float4* hp = reinterpret_cast<const float4*>(h2n) + (size_t)b*(HDIM/4);
    const float4* wp = reinterpret_cast<const float4*>(s_wout);
    float s = 0.f;
    #pragma unroll
    for (int q = lane; q < HDIM/4; q += 32){
        float4 hv = __ldcg(hp + q); float4 w = wp[q];
        s += hv.x*w.x + hv.y*w.y + hv.z*w.z + hv.w*w.w;
    }
    #pragma unroll
    for (int o = 16; o; o >>= 1) s += __shfl_xor_sync(0xffffffffu, s, o);
    if (lane == 0) *dst = s + bout;
}

__global__ void lstm_reset(){ g_bar = 0u; }

__global__ void __launch_bounds__(NTHR, 1) lstm_persist(
    const float* __restrict__ xg,
    const float* __restrict__ Wih1, const float* __restrict__ Whh1,
    const float* __restrict__ bih1, const float* __restrict__ bhh1,
    const float* __restrict__ Wih2, const float* __restrict__ Whh2,
    const float* __restrict__ bih2, const float* __restrict__ bhh2,
    const float* __restrict__ Wout, const float* __restrict__ boutp,
    float* __restrict__ outg)
{
    extern __shared__ float sm[];
    float* s_w1   = sm + OFF_W1;
    float* s_w2i  = sm + OFF_W2I;
    float* s_w2h  = sm + OFF_W2H;
    float* s_wout = sm + OFF_WOUT;
    float* s_wih1 = sm + OFF_WIH1;
    float* s_b1   = sm + OFF_B1;
    float* s_b2   = sm + OFF_B2;
    float* s_c1   = sm + OFF_C1;
    float* s_c2   = sm + OFF_C2;
    float* s_xs   = sm + OFF_XS;
    float* s_red  = sm + OFF_RED;
    float* s_bout = sm + OFF_BOUT;
    unsigned long long* s_red2 =
        reinterpret_cast<unsigned long long*>(sm + OFF_RED2);

    const int tid = threadIdx.x;
    const int blk = blockIdx.x;
    const int U0  = blk * 4;
    const int u   = tid & 3;
    const int bg  = (tid >> 2) & 31;
    const int kc  = tid >> 7;           // 0..3
    const int b0  = bg * 4;
    const int k0  = kc * (HDIM/4);

    // ---- one-time staging: dup'd weight layout [k][u][g][2] ----
    {
        for (int idx = tid; idx < 16*128; idx += NTHR){
            int r = idx >> 7, k4 = idx & 127;     // r = uu*4+gg
            int uu = r >> 2, gg = r & 3;
            int j = gg*HDIM + U0 + uu;
            int base = uu*8 + gg*2;
            float4 a = reinterpret_cast<const float4*>(Whh1 + (size_t)j*HDIM)[k4];
            float4 b = reinterpret_cast<const float4*>(Wih2 + (size_t)j*HDIM)[k4];
            float4 c = reinterpret_cast<const float4*>(Whh2 + (size_t)j*HDIM)[k4];
            const float av[4] = {a.x,a.y,a.z,a.w};
            const float bv[4] = {b.x,b.y,b.z,b.w};
            const float cv[4] = {c.x,c.y,c.z,c.w};
            #pragma unroll
            for (int cck = 0; cck < 4; ++cck){
                int d = (4*k4 + cck)*32 + base;
                s_w1 [d] = av[cck]; s_w1 [d+1] = av[cck];
                s_w2i[d] = bv[cck]; s_w2i[d+1] = bv[cck];
                s_w2h[d] = cv[cck]; s_w2h[d+1] = cv[cck];
            }
        }
        if (tid < 16){
            int uu = tid >> 2, gg = tid & 3;
            int j = gg*HDIM + U0 + uu;
            s_wih1[tid] = Wih1[j];
            s_b1[tid]   = bih1[j] + bhh1[j];
            s_b2[tid]   = bih2[j] + bhh2[j];
        }
        if (tid < 128)
            reinterpret_cast<float4*>(s_wout)[tid] =
                reinterpret_cast<const float4*>(Wout)[tid];
        if (tid == 0) s_bout[0] = boutp[0];
        if (tid < 512){ s_c1[tid] = 0.f; s_c2[tid] = 0.f; }
        for (int i = tid; i < 4*BDIM; i += NTHR){
            int kk = U0 + (i >> 7), bb = i & 127;
            size_t o  = (size_t)kk*BDIM + bb;
            size_t on = (size_t)bb*HDIM + kk;
            g_h1t[o] = 0.f; g_h1t[KH+o] = 0.f;
            g_h2t[o] = 0.f; g_h2t[KH+o] = 0.f;
            g_h2n[on]= 0.f; g_h2n[KH+on]= 0.f;
        }
    }
    unsigned gen = 0;
    grid_barrier(gen);

    for (int t = 0; t < TOT; ++t){
        const int cur = t & 1, prv = cur ^ 1;
        const float* h1r  = g_h1t + (size_t)prv*KH;
        float*       h1w  = g_h1t + (size_t)cur*KH;
        const float* h2r  = g_h2t + (size_t)prv*KH;
        float*       h2w  = g_h2t + (size_t)cur*KH;
        const float* h2nr = g_h2n + (size_t)prv*KH;
        float*       h2nw = g_h2n + (size_t)cur*KH;

        // Phase X: x_t -> s_xs; emit out(t-1)
        if (t < TIN){
            if (tid < BDIM) s_xs[tid] = xg[(size_t)tid*TIN + t];
            if (t > 0 && tid < 32)
                out_one(h2nr, s_wout, s_bout[0], blk, outg + (size_t)blk*TOT + (t-1));
        } else {
            int b = tid & 127, q4 = tid >> 7;
            const float* hp = h2r + (size_t)q4*(HDIM/4)*BDIM + b;
            const float* wp = s_wout + q4*(HDIM/4);
            float s = 0.f;
            #pragma unroll 8
            for (int q = 0; q < HDIM/4; ++q)
                s += __ldcg(hp + (size_t)q*BDIM) * wp[q];
            s_red[tid] = s;
            __syncthreads();
            if (tid < BDIM)
                s_xs[tid] = s_red[tid] + s_red[tid+128] + s_red[tid+256]
                          + s_red[tid+384] + s_bout[0];
        }
        __syncthreads();
        if (t >= TIN && tid == 0) outg[(size_t)blk*TOT + (t-1)] = s_xs[blk];

        // Phase 1: layer-1
        {
            unsigned long long acc[4][2] = {};
            gemm2(s_w1, h1r, acc, u, b0, k0);
            ksplit_reduce(s_red2, acc, tid, kc);
            if (kc == 0){
                float4 hv; float* hvp = &hv.x;
                float4 cold = *reinterpret_cast<float4*>(&s_c1[u*BDIM + b0]);
                float* cop = &cold.x;
                #pragma unroll
                for (int bi = 0; bi < 4; ++bi){
                    int p = bi >> 1;
                    float ai = (bi & 1) ? hi32(acc[0][p]) : lo32(acc[0][p]);
                    float af = (bi & 1) ? hi32(acc[1][p]) : lo32(acc[1][p]);
                    float ag = (bi & 1) ? hi32(acc[2][p]) : lo32(acc[2][p]);
                    float ao = (bi & 1) ? hi32(acc[3][p]) : lo32(acc[3][p]);
                    float xv = s_xs[b0 + bi];
                    float vi = ai + s_b1[u*4+0] + xv*s_wih1[u*4+0];
                    float vf = af + s_b1[u*4+1] + xv*s_wih1[u*4+1];
                    float vg = ag + s_b1[u*4+2] + xv*s_wih1[u*4+2];
                    float vo = ao + s_b1[u*4+3] + xv*s_wih1[u*4+3];
                    float c  = sigf(vf)*cop[bi] + sigf(vi)*tfast(vg);
                    cop[bi]  = c;
                    hvp[bi]  = sigf(vo)*tfast(c);
                }
                *reinterpret_cast<float4*>(&s_c1[u*BDIM + b0]) = cold;
                *reinterpret_cast<float4*>(&h1w[(size_t)(U0+u)*BDIM + b0]) = hv;
            }
        }
        grid_barrier(gen);

        // Phase 2: layer-2 (K = h1_new then h2_prev)
        {
            unsigned long long acc[4][2] = {};
            gemm2(s_w2i, h1w, acc, u, b0, k0);
            gemm2(s_w2h, h2r, acc, u, b0, k0);
            ksplit_reduce(s_red2, acc, tid, kc);
            if (kc == 0){
                float4 hv; float* hvp = &hv.x;
                float4 cold = *reinterpret_cast<float4*>(&s_c2[u*BDIM + b0]);
                float* cop = &cold.x;
                #pragma unroll
                for (int bi = 0; bi < 4; ++bi){
                    int p = bi >> 1;
                    float ai = (bi & 1) ? hi32(acc[0][p]) : lo32(acc[0][p]);
                    float af = (bi & 1) ? hi32(acc[1][p]) : lo32(acc[1][p]);
                    float ag = (bi & 1) ? hi32(acc[2][p]) : lo32(acc[2][p]);
                    float ao = (bi & 1) ? hi32(acc[3][p]) : lo32(acc[3][p]);
                    float vi = ai + s_b2[u*4+0];
                    float vf = af + s_b2[u*4+1];
                    float vg = ag + s_b2[u*4+2];
                    float vo = ao + s_b2[u*4+3];
                    float c  = sigf(vf)*cop[bi] + sigf(vi)*tfast(vg);
                    cop[bi]  = c;
                    hvp[bi]  = sigf(vo)*tfast(c);
                }
                *reinterpret_cast<float4*>(&s_c2[u*BDIM + b0]) = cold;
                *reinterpret_cast<float4*>(&h2w[(size_t)(U0+u)*BDIM + b0]) = hv;
                h2nw[(size_t)(b0+0)*HDIM + U0 + u] = hv.x;
                h2nw[(size_t)(b0+1)*HDIM + U0 + u] = hv.y;
                h2nw[(size_t)(b0+2)*HDIM + U0 + u] = hv.z;
                h2nw[(size_t)(b0+3)*HDIM + U0 + u] = hv.w;
            }
        }
        grid_barrier(gen);
    }

    if (tid < 32)
        out_one(g_h2n + (size_t)((TOT-1)&1)*KH, s_wout, s_bout[0],
                blk, outg + (size_t)blk*TOT + (TOT-1));
}

extern "C" void kernel_launch(void* const* d_in, const int* in_sizes, int n_in,
                              void* d_out, int out_size){
    (void)in_sizes; (void)n_in; (void)out_size;
    static int smem_ok = 0;
    if (!smem_ok){
        cudaFuncSetAttribute(lstm_persist,
                             cudaFuncAttributeMaxDynamicSharedMemorySize, SMEM_BYTES);
        smem_ok = 1;
    }
    const float* x    = (const float*)d_in[0];
    const float* Wih1 = (const float*)d_in[1];
    const float* Whh1 = (const float*)d_in[2];
    const float* bih1 = (const float*)d_in[3];
    const float* bhh1 = (const float*)d_in[4];
    const float* Wih2 = (const float*)d_in[5];
    const float* Whh2 = (const float*)d_in[6];
    const float* bih2 = (const float*)d_in[7];
    const float* bhh2 = (const float*)d_in[8];
    const float* Wout = (const float*)d_in[9];
    const float* bout = (const float*)d_in[10];
    float* out = (float*)d_out;

    lstm_reset<<<1, 1>>>();
    lstm_persist<<<NBLK, NTHR, SMEM_BYTES>>>(
        x, Wih1, Whh1, bih1, bhh1, Wih2, Whh2, bih2, bhh2, Wout, bout, out);
}

// round 13
// speedup vs baseline: 4.8473x; 3.9170x over previous
#include <cuda_runtime.h>
#include <cuda_fp16.h>
#include <cstdint>

#define NBLK 128
#define NTHR 256
#define HDIM 512
#define BDIM 128
#define TIN  512
#define TOT  544
#define BH   (BDIM*HDIM)

// SMEM byte offsets (all 1KB-aligned)
#define SA    0           // A tile: 128 rows x 1024B fp16, swizzled
#define SW1   131072      // 3 weight tiles: 16 rows x 1024B fp16 each
#define SW2I  147456
#define SW2H  163840
#define SGATE 180224      // 8 warps x 16x16 f32 = 8192
#define SMISC 188416
#define SXS   (SMISC)         // 128 f32
#define SRED  (SMISC+512)     // 256 f32
#define SB1   (SMISC+1536)    // 16 f32
#define SWIH  (SMISC+1600)    // 16 f32
#define SB2   (SMISC+1664)    // 16 f32
#define SBOUT (SMISC+1728)    // 1 f32
#define SMEM_BYTES (SMISC+2048)

__device__ __half  g_h1f[2][BH];   // [buf][b][k] fp16
__device__ __half  g_h2f[2][BH];
__device__ float   g_h2n[2][BH];   // [buf][b][k] fp32 (output dots)
__device__ float   g_h2t[2][BH];   // [buf][k][b] fp32 (future-phase dot)
__device__ unsigned g_bar;

static __device__ __forceinline__ uint32_t smem_u32(const void* p){
    uint32_t a;
    asm("{ .reg .u64 t; cvta.to.shared.u64 t, %1; cvt.u32.u64 %0, t; }" : "=r"(a) : "l"(p));
    return a;
}
static __device__ __forceinline__ float sigf(float x){ return 1.0f/(1.0f+__expf(-x)); }
static __device__ __forceinline__ float tfast(float x){ return 2.0f*sigf(2.0f*x) - 1.0f; }

static __device__ __forceinline__ void grid_barrier(unsigned& gen){
    __threadfence();
    __syncthreads();
    if (threadIdx.x == 0){
        unsigned target = gen + NBLK;
        atomicAdd(&g_bar, 1u);
        unsigned v;
        do { asm volatile("ld.acquire.gpu.u32 %0, [%1];" : "=r"(v) : "l"(&g_bar)); }
        while (v < target);
    }
    gen += NBLK;
    __syncthreads();
}

#define TEAM_BAR(team) asm volatile("bar.sync %0, 128;" :: "r"(1+(team)) : "memory")

// load 64 batch rows (team half) of h [.][512] fp16 into SMEM A tile, L2-only.
// Swizzle XOR applied to the FULL summed address (matches all readers).
static __device__ __forceinline__ void load_half(uint32_t saAddr,
                                                 const __half* __restrict__ src,
                                                 int team, int tt){
    #pragma unroll
    for (int j = 0; j < 32; ++j){
        int i  = tt + j*128;                 // 0..4095 16B units in half-tile
        int m  = team*64 + (i >> 6);
        int u8 = i & 63;
        uint32_t dst = (saAddr + (uint32_t)(m*1024 + u8*16)) ^ (uint32_t)((m & 7) << 4);
        const __half* s = src + (size_t)m*HDIM + u8*8;
        asm volatile("cp.async.cg.shared.global [%0], [%1], 16;"
                     :: "r"(dst), "l"(s) : "memory");
    }
    asm volatile("cp.async.commit_group;" ::: "memory");
    asm volatile("cp.async.wait_group 0;" ::: "memory");
}

// warp GEMM: acc[2][4] += A(16 rows x 512) * B(16 x 512)^T, k-tiles of 16.
// Swizzle XOR applied per k-tile on the fully-summed address (bug fix vs R11).
static __device__ __forceinline__ void warp_gemm(float (&acc)[2][4],
                                                 uint32_t aBase, uint32_t aswz,
                                                 uint32_t bBase, uint32_t bswz){
    #pragma unroll 8
    for (int kt = 0; kt < 32; ++kt){
        uint32_t aa = (aBase + (uint32_t)(kt*32)) ^ aswz;
        uint32_t ba = (bBase + (uint32_t)(kt*32)) ^ bswz;
        uint32_t a0,a1,a2,a3, b0,b1,b2,b3;
        asm volatile("ldmatrix.sync.aligned.m8n8.x4.shared.b16 {%0,%1,%2,%3}, [%4];"
            : "=r"(a0),"=r"(a1),"=r"(a2),"=r"(a3) : "r"(aa));
        asm volatile("ldmatrix.sync.aligned.m8n8.x4.shared.b16 {%0,%1,%2,%3}, [%4];"
            : "=r"(b0),"=r"(b1),"=r"(b2),"=r"(b3) : "r"(ba));
        asm volatile("mma.sync.aligned.m16n8k16.row.col.f32.f16.f16.f32 "
            "{%0,%1,%2,%3}, {%4,%5,%6,%7}, {%8,%9}, {%0,%1,%2,%3};"
            : "+f"(acc[0][0]),"+f"(acc[0][1]),"+f"(acc[0][2]),"+f"(acc[0][3])
            : "r"(a0),"r"(a1),"r"(a2),"r"(a3), "r"(b0),"r"(b1));
        asm volatile("mma.sync.aligned.m16n8k16.row.col.f32.f16.f16.f32 "
            "{%0,%1,%2,%3}, {%4,%5,%6,%7}, {%8,%9}, {%0,%1,%2,%3};"
            : "+f"(acc[1][0]),"+f"(acc[1][1]),"+f"(acc[1][2]),"+f"(acc[1][3])
            : "r"(a0),"r"(a1),"r"(a2),"r"(a3), "r"(b2),"r"(b3));
    }
}

// out[b] = dot(h2n[b,:], Wout) + bias; warp 0 (tid<32)
static __device__ __forceinline__ void out_one(
    const float* __restrict__ h2n, const float* __restrict__ Wout,
    float bout, int b, float* dst)
{
    const int lane = threadIdx.x;
    const float4* hp = reinterpret_cast<const float4*>(h2n) + (size_t)b*(HDIM/4);
    const float4* wp = reinterpret_cast<const float4*>(Wout);
    float s = 0.f;
    #pragma unroll
    for (int q = lane; q < HDIM/4; q += 32){
        float4 hv = __ldcg(hp + q); float4 w = __ldg(wp + q);
        s += hv.x*w.x + hv.y*w.y + hv.z*w.z + hv.w*w.w;
    }
    #pragma unroll
    for (int o = 16; o; o >>= 1) s += __shfl_xor_sync(0xffffffffu, s, o);
    if (lane == 0) *dst = s + bout;
}

__global__ void lstm_reset(){ g_bar = 0u; }

__global__ void __launch_bounds__(NTHR, 1) lstm_persist(
    const float* __restrict__ xg,
    const float* __restrict__ Wih1, const float* __restrict__ Whh1,
    const float* __restrict__ bih1, const float* __restrict__ bhh1,
    const float* __restrict__ Wih2, const float* __restrict__ Whh2,
    const float* __restrict__ bih2, const float* __restrict__ bhh2,
    const float* __restrict__ Wout, const float* __restrict__ boutp,
    float* __restrict__ outg)
{
    extern __shared__ __align__(128) char sm[];
    const uint32_t sb = smem_u32(sm);
    float* s_gate = reinterpret_cast<float*>(sm + SGATE);
    float* s_xs   = reinterpret_cast<float*>(sm + SXS);
    float* s_red  = reinterpret_cast<float*>(sm + SRED);
    float* s_b1   = reinterpret_cast<float*>(sm + SB1);
    float* s_wih  = reinterpret_cast<float*>(sm + SWIH);
    float* s_b2   = reinterpret_cast<float*>(sm + SB2);
    float* s_bo   = reinterpret_cast<float*>(sm + SBOUT);

    const int tid  = threadIdx.x;
    const int blk  = blockIdx.x;
    const int U0   = blk * 4;
    const int wid  = tid >> 5;
    const int lane = tid & 31;
    const int team = tid >> 7;
    const int tt   = tid & 127;

    // per-lane ldmatrix base addresses (XOR swizzle applied per-access in warp_gemm)
    const int grp = lane >> 3, l7 = lane & 7;
    const int am  = (wid << 4) + l7 + ((grp & 1) << 3);
    const uint32_t aBase = sb + SA + (uint32_t)(am*1024 + ((grp >> 1) << 4));
    const uint32_t aswz  = (uint32_t)((am & 7) << 4);
    const int bn  = l7 + ((grp >> 1) << 3);
    const uint32_t bOff  = (uint32_t)(bn*1024 + ((grp & 1) << 4));
    const uint32_t bswz  = (uint32_t)((bn & 7) << 4);
    const uint32_t bB1   = sb + SW1  + bOff;
    const uint32_t bB2i  = sb + SW2I + bOff;
    const uint32_t bB2h  = sb + SW2H + bOff;

    // ---- one-time staging: weights via st.shared.u16 at XOR'ed full addresses ----
    for (int idx = tid; idx < 16*HDIM; idx += NTHR){
        int n = idx >> 9, k = idx & 511;
        int uu = n >> 2, gg = n & 3;
        size_t j = (size_t)(gg*HDIM + U0 + uu) * HDIM + k;
        uint32_t rel = (uint32_t)(n*1024 + 2*k);
        uint32_t sw  = (uint32_t)((n & 7) << 4);
        unsigned short v1 = __half_as_ushort(__float2half(Whh1[j]));
        unsigned short v2 = __half_as_ushort(__float2half(Wih2[j]));
        unsigned short v3 = __half_as_ushort(__float2half(Whh2[j]));
        asm volatile("st.shared.u16 [%0], %1;" :: "r"((sb + SW1  + rel) ^ sw), "h"(v1));
        asm volatile("st.shared.u16 [%0], %1;" :: "r"((sb + SW2I + rel) ^ sw), "h"(v2));
        asm volatile("st.shared.u16 [%0], %1;" :: "r"((sb + SW2H + rel) ^ sw), "h"(v3));
    }
    if (tid < 16){
        int uu = tid >> 2, gg = tid & 3;
        int j = gg*HDIM + U0 + uu;
        s_b1[tid]  = bih1[j] + bhh1[j];
        s_b2[tid]  = bih2[j] + bhh2[j];
        s_wih[tid] = Wih1[j];
    }
    if (tid == 0) s_bo[0] = boutp[0];
    for (int i = tid; i < 4*BDIM; i += NTHR){
        int kk = U0 + (i >> 7), bb = i & 127;
        size_t on = (size_t)bb*HDIM + kk;
        size_t ot = (size_t)kk*BDIM + bb;
        g_h1f[0][on] = __float2half(0.f); g_h1f[1][on] = __float2half(0.f);
        g_h2f[0][on] = __float2half(0.f); g_h2f[1][on] = __float2half(0.f);
        g_h2n[0][on] = 0.f; g_h2n[1][on] = 0.f;
        g_h2t[0][ot] = 0.f; g_h2t[1][ot] = 0.f;
    }
    unsigned gen = 0;
    grid_barrier(gen);

    // epilogue-side indices
    const int eg = lane >> 2, etq = lane & 3;       // staging write coords
    const int bl = lane >> 1, u0 = (lane & 1) * 2;  // staging read coords
    const int bglob = (wid << 4) + bl;
    float* st = s_gate + wid*256;
    float c1a = 0.f, c1b = 0.f, c2a = 0.f, c2b = 0.f;

    for (int t = 0; t < TOT; ++t){
        const int cur = t & 1, prv = cur ^ 1;

        // ---- Phase X ----
        if (t < TIN){
            if (tid < BDIM) s_xs[tid] = xg[(size_t)tid*TIN + t];
            if (t > 0 && tid < 32)
                out_one(g_h2n[prv], Wout, s_bo[0], blk, outg + (size_t)blk*TOT + (t-1));
        } else {
            int b = tid & 127, half = tid >> 7;
            const float* hp = g_h2t[prv] + (size_t)half*(HDIM/2)*BDIM + b;
            const float* wp = Wout + half*(HDIM/2);
            float s = 0.f;
            #pragma unroll 8
            for (int q = 0; q < HDIM/2; ++q)
                s += __ldcg(hp + (size_t)q*BDIM) * __ldg(wp + q);
            s_red[tid] = s;
            __syncthreads();
            if (tid < BDIM) s_xs[tid] = s_red[tid] + s_red[tid+128] + s_bo[0];
        }
        __syncthreads();
        if (t >= TIN && tid == 0) outg[(size_t)blk*TOT + (t-1)] = s_xs[blk];

        // ---- P1: gates1 = h1_prev @ W_hh1^T ----
        {
            load_half(sb + SA, g_h1f[prv], team, tt);
            TEAM_BAR(team);
            float acc[2][4] = {};
            warp_gemm(acc, aBase, aswz, bB1, bswz);
            *reinterpret_cast<float2*>(&st[eg*16      + 2*etq]) = make_float2(acc[0][0], acc[0][1]);
            *reinterpret_cast<float2*>(&st[(eg+8)*16  + 2*etq]) = make_float2(acc[0][2], acc[0][3]);
            *reinterpret_cast<float2*>(&st[eg*16 + 8  + 2*etq]) = make_float2(acc[1][0], acc[1][1]);
            *reinterpret_cast<float2*>(&st[(eg+8)*16+8+ 2*etq]) = make_float2(acc[1][2], acc[1][3]);
            __syncwarp();
            float4 gA = *reinterpret_cast<float4*>(&st[bl*16 + u0*4]);
            float4 gB = *reinterpret_cast<float4*>(&st[bl*16 + u0*4 + 4]);
            float xv  = s_xs[bglob];
            float4 bb0 = *reinterpret_cast<float4*>(&s_b1[u0*4]);
            float4 bb1 = *reinterpret_cast<float4*>(&s_b1[u0*4 + 4]);
            float4 ww0 = *reinterpret_cast<float4*>(&s_wih[u0*4]);
            float4 ww1 = *reinterpret_cast<float4*>(&s_wih[u0*4 + 4]);
            float vi = gA.x + bb0.x + xv*ww0.x;
            float vf = gA.y + bb0.y + xv*ww0.y;
            float vg = gA.z + bb0.z + xv*ww0.z;
            float vo = gA.w + bb0.w + xv*ww0.w;
            c1a = sigf(vf)*c1a + sigf(vi)*tfast(vg);
            float h0 = sigf(vo)*tfast(c1a);
            vi = gB.x + bb1.x + xv*ww1.x;
            vf = gB.y + bb1.y + xv*ww1.y;
            vg = gB.z + bb1.z + xv*ww1.z;
            vo = gB.w + bb1.w + xv*ww1.w;
            c1b = sigf(vf)*c1b + sigf(vi)*tfast(vg);
            float h1v = sigf(vo)*tfast(c1b);
            *reinterpret_cast<__half2*>(&g_h1f[cur][(size_t)bglob*HDIM + U0 + u0]) =
                __floats2half2_rn(h0, h1v);
        }
        grid_barrier(gen);

        // ---- P2: gates2 = h1_new @ W_ih2^T + h2_prev @ W_hh2^T ----
        {
            float acc[2][4] = {};
            load_half(sb + SA, g_h1f[cur], team, tt);
            TEAM_BAR(team);
            warp_gemm(acc, aBase, aswz, bB2i, bswz);
            TEAM_BAR(team);                       // team done reading A half
            load_half(sb + SA, g_h2f[prv], team, tt);
            TEAM_BAR(team);
            warp_gemm(acc, aBase, aswz, bB2h, bswz);
            *reinterpret_cast<float2*>(&st[eg*16      + 2*etq]) = make_float2(acc[0][0], acc[0][1]);
            *reinterpret_cast<float2*>(&st[(eg+8)*16  + 2*etq]) = make_float2(acc[0][2], acc[0][3]);
            *reinterpret_cast<float2*>(&st[eg*16 + 8  + 2*etq]) = make_float2(acc[1][0], acc[1][1]);
            *reinterpret_cast<float2*>(&st[(eg+8)*16+8+ 2*etq]) = make_float2(acc[1][2], acc[1][3]);
            __syncwarp();
            float4 gA = *reinterpret_cast<float4*>(&st[bl*16 + u0*4]);
            float4 gB = *reinterpret_cast<float4*>(&st[bl*16 + u0*4 + 4]);
            float4 bb0 = *reinterpret_cast<float4*>(&s_b2[u0*4]);
            float4 bb1 = *reinterpret_cast<float4*>(&s_b2[u0*4 + 4]);
            float vi = gA.x + bb0.x, vf = gA.y + bb0.y;
            float vg = gA.z + bb0.z, vo = gA.w + bb0.w;
            c2a = sigf(vf)*c2a + sigf(vi)*tfast(vg);
            float h0 = sigf(vo)*tfast(c2a);
            vi = gB.x + bb1.x; vf = gB.y + bb1.y;
            vg = gB.z + bb1.z; vo = gB.w + bb1.w;
            c2b = sigf(vf)*c2b + sigf(vi)*tfast(vg);
            float h1v = sigf(vo)*tfast(c2b);
            size_t base = (size_t)bglob*HDIM + U0 + u0;
            *reinterpret_cast<__half2*>(&g_h2f[cur][base]) = __floats2half2_rn(h0, h1v);
            *reinterpret_cast<float2*>(&g_h2n[cur][base])  = make_float2(h0, h1v);
            g_h2t[cur][(size_t)(U0 + u0    )*BDIM + bglob] = h0;
            g_h2t[cur][(size_t)(U0 + u0 + 1)*BDIM + bglob] = h1v;
        }
        grid_barrier(gen);
    }

    if (tid < 32)
        out_one(g_h2n[(TOT-1)&1], Wout, s_bo[0], blk, outg + (size_t)blk*TOT + (TOT-1));
}

extern "C" void kernel_launch(void* const* d_in, const int* in_sizes, int n_in,
                              void* d_out, int out_size){
    (void)in_sizes; (void)n_in; (void)out_size;
    cudaFuncSetAttribute(lstm_persist,
                         cudaFuncAttributeMaxDynamicSharedMemorySize, SMEM_BYTES);
    const float* x    = (const float*)d_in[0];
    const float* Wih1 = (const float*)d_in[1];
    const float* Whh1 = (const float*)d_in[2];
    const float* bih1 = (const float*)d_in[3];
    const float* bhh1 = (const float*)d_in[4];
    const float* Wih2 = (const float*)d_in[5];
    const float* Whh2 = (const float*)d_in[6];
    const float* bih2 = (const float*)d_in[7];
    const float* bhh2 = (const float*)d_in[8];
    const float* Wout = (const float*)d_in[9];
    const float* bout = (const float*)d_in[10];
    float* out = (float*)d_out;

    lstm_reset<<<1, 1>>>();
    lstm_persist<<<NBLK, NTHR, SMEM_BYTES>>>(
        x, Wih1, Whh1, bih1, bhh1, Wih2, Whh2, bih2, bhh2, Wout, bout, out);
}